// round 13
// baseline (speedup 1.0000x reference)
#include <cuda_runtime.h>
#include <cuda_fp16.h>
#include <math.h>
#include <stdint.h>

// Problem constants
#define TT   32
#define BB   32
#define NIN  64
#define HH   256
#define NOUT 64
#define EMAX 9984          // 78 * 128 exactly
#define NTILES 78
#define CLMIN (-2.0f)
#define CLMAX ( 2.0f)

// ------- device state (no allocations allowed) -------
// Error-row state, fp16, tiled: idx = ((tile*16 + chunk)*128 + row)*16 + h
__device__ __half g_state[2][(size_t)BB * EMAX * HH];
// B' = fp16(lam ⊙ W_hh^T), smem-image (pitch 24 halves)
__device__ __half g_Bp[(size_t)BB * 2 * 16 * 3072];
// B'o = fp16(lam_31 ⊙ W_o), [b][chunk16][row64][pitch24]
__device__ __half g_Bo[(size_t)BB * 16 * 64 * 24];
__device__ float g_rad[2][BB * HH];       // parity ping-pong
__device__ float g_headpre[2][BB * HH];   // parity ping-pong
__device__ float g_delta[BB * HH];
__device__ float g_headpost[BB * HH];
__device__ float g_radout[BB * NOUT];
__device__ int   g_flag[BB * 2];          // B'-ready flag per (b, nhalf)

// ------- helpers -------
__device__ __forceinline__ uint32_t smem_u32(const void* p) {
    uint32_t a;
    asm("{ .reg .u64 t; cvta.to.shared.u64 t, %1; cvt.u32.u64 %0, t; }" : "=r"(a) : "l"(p));
    return a;
}
__device__ __forceinline__ void ldsm4(unsigned r[4], uint32_t addr) {
    asm volatile("ldmatrix.sync.aligned.m8n8.x4.shared.b16 {%0,%1,%2,%3}, [%4];"
                 : "=r"(r[0]), "=r"(r[1]), "=r"(r[2]), "=r"(r[3]) : "r"(addr));
}
__device__ __forceinline__ void mma_f16(float* c, const unsigned a[4],
                                        unsigned b0, unsigned b1) {
    asm volatile("mma.sync.aligned.m16n8k16.row.col.f32.f16.f16.f32 "
                 "{%0,%1,%2,%3},{%4,%5,%6,%7},{%8,%9},{%0,%1,%2,%3};"
                 : "+f"(c[0]), "+f"(c[1]), "+f"(c[2]), "+f"(c[3])
                 : "r"(a[0]), "r"(a[1]), "r"(a[2]), "r"(a[3]), "r"(b0), "r"(b1));
}
__device__ __forceinline__ void cpa16(uint32_t dst, const void* src) {
    asm volatile("cp.async.cg.shared.global [%0], [%1], 16;" :: "r"(dst), "l"(src));
}
// DeepZ tanh transformer pieces from (head, rad)
__device__ __forceinline__ void deepz(float head, float rad,
                                      float& lam, float& mu, float& delta) {
    float l = head - rad, u = head + rad;
    float tl = tanhf(l), tu = tanhf(u);
    lam = fminf(1.f - tl * tl, 1.f - tu * tu);
    mu    = 0.5f * (tu + tl - lam * (u + l));
    delta = 0.5f * (tu - tl - lam * (u - l));
}
__device__ __forceinline__ void flag_wait(int idx, int t) {
    int v;
    do {
        asm volatile("ld.acquire.gpu.global.b32 %0, [%1];"
                     : "=r"(v) : "l"(&g_flag[idx]) : "memory");
    } while (v < t);
}

#define TILE_BYTES 6144      // 128 rows * 48B pitch
#define STG_BYTES  12288
#define GT_SMEM    (3 * STG_BYTES)
#define FIN_STG    9216      // A 6144 + B 3072
#define FIN_SMEM   (3 * FIN_STG)

// ---------------------------------------------------------------------------
// Step 0: initial x-block rows (fp16 tiled), head_pre_0, rad[0], zero flags
// ---------------------------------------------------------------------------
__global__ void step0_kernel(const float* __restrict__ X,
                             const float* __restrict__ eps,
                             const float* __restrict__ W_ih,
                             const float* __restrict__ b_ih,
                             const float* __restrict__ b_hh)
{
    int b = blockIdx.x;
    int tid = threadIdx.x;
    __shared__ float s_hx[NIN], s_w[NIN];
    if (tid < 2) g_flag[b * 2 + tid] = 0;
    if (tid < NIN) {
        float x = X[b * NIN + tid];
        float e = eps[b];
        float l = fmaxf(x - e, CLMIN);
        float u = fminf(x + e, CLMAX);
        s_hx[tid] = 0.5f * (l + u);
        s_w[tid]  = 0.5f * (u - l);
    }
    __syncthreads();
    int h = tid;
    float hp = b_ih[h] + b_hh[h];
    float rad = 0.f;
    __half* st = g_state[0] + (size_t)b * EMAX * HH;
    int chunk = h >> 4, kh = h & 15;
#pragma unroll 8
    for (int i = 0; i < NIN; i++) {
        float wv = W_ih[i * HH + h];
        float rowv = s_w[i] * wv;
        hp += s_hx[i] * wv;
        __half hv = __float2half_rn(rowv);
        rad += fabsf(__half2float(hv));
        st[((size_t)chunk * 128 + i) * 16 + kh] = hv;
    }
    g_headpre[0][b * HH + h] = hp;
    g_rad[0][b * HH + h] = rad;
}

// ---------------------------------------------------------------------------
// Fused step kernel: B' prep (bx==0, flag-release) + gemm tiles + append +
// head/rad recurrence. grid (mtiles + 3, 2, BB), 256 threads.
//   bx == 0          : prep B'[b,nhalf] (vectorized), zero rad[par] cols, flag=t
//   bx in [1,mtiles] : gemm tile mtile=bx-1 (flag-gated)
//   bx == mtiles+1   : fresh diag + x rows append (no gate)
//   bx == mtiles+2   : head recurrence + fresh/x rad parts (flag-gated)
// ---------------------------------------------------------------------------
__global__ void __launch_bounds__(256, 2)
step_kernel(const float* __restrict__ X,
            const float* __restrict__ eps,
            const float* __restrict__ W_ih,
            const float* __restrict__ W_hh,
            const float* __restrict__ b_ih,
            const float* __restrict__ b_hh,
            int t, int Eprev, int pp)
{
    extern __shared__ char sm[];
    int b = blockIdx.z;
    int nhalf = blockIdx.y;
    int nbase = nhalf * 128;
    int tid = threadIdx.x;
    int mtiles = gridDim.x - 3;
    int bx = blockIdx.x;
    int par = pp ^ 1;
    int fidx = b * 2 + nhalf;
    const float* Xt = X + (size_t)t * BB * NIN;
    __half* O = g_state[par] + (size_t)b * EMAX * HH;

    if (bx == 0) {
        // ---- B' prep (vectorized 16B stores) + rad[par] zero ----
        float* s_lam = (float*)sm;     // 256
        {
            float lam, mu, de;
            deepz(g_headpre[pp][b * HH + tid], g_rad[pp][b * HH + tid], lam, mu, de);
            s_lam[tid] = lam;
        }
        if (tid < 128) g_rad[par][b * HH + nbase + tid] = 0.f;
        __syncthreads();
        int row = tid >> 1, part = tid & 1;
        __half* dst = g_Bp + (size_t)fidx * 16 * 3072;
#pragma unroll
        for (int c = 0; c < 16; c++) {
            __half hv[8];
#pragma unroll
            for (int j = 0; j < 8; j++) {
                int k = c * 16 + part * 8 + j;
                hv[j] = __float2half_rn(s_lam[k] * W_hh[k * HH + nbase + row]);
            }
            *(uint4*)&dst[(size_t)c * 3072 + row * 24 + part * 8] = *(uint4*)hv;
        }
        __threadfence();
        __syncthreads();
        if (tid == 0)
            asm volatile("st.release.gpu.global.b32 [%0], %1;"
                         :: "l"(&g_flag[fidx]), "r"(t) : "memory");
        return;
    }
    if (bx == mtiles + 1) {
        // ---- fresh diag rows + x rows for cols [nbase, nbase+128), vectorized ----
        float* sd = (float*)sm;            // 256 delta
        float* sw = (float*)sm + 256;      // 64 x-widths
        {
            float lam, mu, de;
            deepz(g_headpre[pp][b * HH + tid], g_rad[pp][b * HH + tid], lam, mu, de);
            sd[tid] = de;
        }
        if (tid < NIN) {
            float x = Xt[b * NIN + tid];
            float e = eps[b];
            float l = fmaxf(x - e, CLMIN), u = fminf(x + e, CLMAX);
            sw[tid] = 0.5f * (u - l);
        }
        __syncthreads();
        // fresh: 256 rows x 8 col-groups of 16
#pragma unroll
        for (int task = tid; task < 2048; task += 256) {
            int i = task >> 3, g = task & 7;
            int R = Eprev + i;
            float d = sd[i];
            const float4* wr = (const float4*)&W_hh[i * HH + nbase + g * 16];
            __half hv[16];
#pragma unroll
            for (int q = 0; q < 4; q++) {
                float4 v = wr[q];
                hv[q * 4 + 0] = __float2half_rn(d * v.x);
                hv[q * 4 + 1] = __float2half_rn(d * v.y);
                hv[q * 4 + 2] = __float2half_rn(d * v.z);
                hv[q * 4 + 3] = __float2half_rn(d * v.w);
            }
            int chunk = nhalf * 8 + g;
            __half* dp = &O[(((size_t)(R >> 7) * 16 + chunk) * 128 + (R & 127)) * 16];
            *(uint4*)&dp[0] = *(uint4*)&hv[0];
            *(uint4*)&dp[8] = *(uint4*)&hv[8];
        }
        // x rows: 64 rows x 8 col-groups
#pragma unroll
        for (int task = tid; task < 512; task += 256) {
            int i = task >> 3, g = task & 7;
            int R = Eprev + 256 + i;
            float d = sw[i];
            const float4* wr = (const float4*)&W_ih[i * HH + nbase + g * 16];
            __half hv[16];
#pragma unroll
            for (int q = 0; q < 4; q++) {
                float4 v = wr[q];
                hv[q * 4 + 0] = __float2half_rn(d * v.x);
                hv[q * 4 + 1] = __float2half_rn(d * v.y);
                hv[q * 4 + 2] = __float2half_rn(d * v.z);
                hv[q * 4 + 3] = __float2half_rn(d * v.w);
            }
            int chunk = nhalf * 8 + g;
            __half* dp = &O[(((size_t)(R >> 7) * 16 + chunk) * 128 + (R & 127)) * 16];
            *(uint4*)&dp[0] = *(uint4*)&hv[0];
            *(uint4*)&dp[8] = *(uint4*)&hv[8];
        }
        return;
    }
    if (bx == mtiles + 2) {
        // ---- head recurrence + fresh/x rad contributions, h in [nbase,+128) ----
        float* shp = (float*)sm;           // 256 headpost
        float* sdd = (float*)sm + 256;     // 256 |delta|
        float* shx = (float*)sm + 512;     // 64
        float* sw  = (float*)sm + 576;     // 64
        float* red = (float*)sm + 640;     // 512 reduction
        {
            float lam, mu, de;
            float hp0 = g_headpre[pp][b * HH + tid];
            deepz(hp0, g_rad[pp][b * HH + tid], lam, mu, de);
            shp[tid] = lam * hp0 + mu;
            sdd[tid] = fabsf(de);
        }
        if (tid < NIN) {
            float x = Xt[b * NIN + tid];
            float e = eps[b];
            float l = fmaxf(x - e, CLMIN), u = fminf(x + e, CLMAX);
            shx[tid] = 0.5f * (l + u);
            sw[tid]  = 0.5f * (u - l);
        }
        __syncthreads();
        int h = nbase + (tid & 127);
        int seg = tid >> 7;
        float hp = 0.f, radc = 0.f;
        int k0 = seg * 128;
#pragma unroll 8
        for (int k = k0; k < k0 + 128; k++) {
            float wv = W_hh[k * HH + h];
            hp   += shp[k] * wv;
            radc += sdd[k] * fabsf(wv);
        }
        if (seg == 1) {
#pragma unroll 8
            for (int i = 0; i < NIN; i++) {
                float wv = W_ih[i * HH + h];
                hp   += shx[i] * wv;
                radc += sw[i] * fabsf(wv);
            }
        } else {
            hp += b_ih[h] + b_hh[h];
        }
        red[tid] = hp;
        red[tid + 256] = radc;
        __syncthreads();
        if (tid == 0) flag_wait(fidx, t);   // rad[par] must be zeroed
        __syncthreads();
        if (tid < 128) {
            float hpt = red[tid] + red[tid + 128];
            float rct = red[tid + 256] + red[tid + 384];
            g_headpre[par][b * HH + h] = hpt;
            atomicAdd(&g_rad[par][b * HH + h], rct);
        }
        return;
    }

    // ---- gemm tile path ----
    uint32_t smb = smem_u32(sm);
    int mtile = bx - 1;
    int mbase = mtile * 128;
    int M = Eprev;
    const __half* A = g_state[pp] + (size_t)b * EMAX * HH;
    const __half* Bp = g_Bp + (size_t)fidx * 16 * 3072;

    int w = tid >> 5, lane = tid & 31;
    int aRow = tid >> 1, aHalf = tid & 1;
    int bRow0 = tid / 3, bPart0 = tid - bRow0 * 3;
    int g1 = 256 + tid;
    int bRow1 = g1 / 3, bPart1 = g1 - bRow1 * 3;

    // wait for B' (and rad zero) before loading B
    if (tid == 0) flag_wait(fidx, t);
    __syncthreads();

#define ISSUE(c) do {                                                          \
    int _s = (c) % 3;                                                          \
    uint32_t _sa = smb + _s * STG_BYTES;                                       \
    cpa16(_sa + aRow * 48 + aHalf * 16,                                        \
          A + (((size_t)mtile * 16 + (c)) * 128 + aRow) * 16 + aHalf * 8);     \
    uint32_t _sb = _sa + TILE_BYTES;                                           \
    cpa16(_sb + bRow0 * 48 + bPart0 * 16,                                      \
          Bp + (size_t)(c) * 3072 + bRow0 * 24 + bPart0 * 8);                  \
    if (tid < 128)                                                             \
        cpa16(_sb + bRow1 * 48 + bPart1 * 16,                                  \
              Bp + (size_t)(c) * 3072 + bRow1 * 24 + bPart1 * 8);              \
    asm volatile("cp.async.commit_group;");                                    \
} while (0)

    float acc[2][8][4];
#pragma unroll
    for (int mt = 0; mt < 2; mt++)
#pragma unroll
        for (int nt = 0; nt < 8; nt++)
#pragma unroll
            for (int e = 0; e < 4; e++) acc[mt][nt][e] = 0.f;

    ISSUE(0);
    ISSUE(1);

    int wm = w >> 1, wn = w & 1;
    uint32_t aL = (uint32_t)((wm * 32 + (lane & 15)) * 48 + ((lane >> 4) << 4));
    uint32_t bL = (uint32_t)((wn * 64 + (lane & 15)) * 48 + ((lane >> 4) << 4));

    for (int c = 0; c < 16; c++) {
        asm volatile("cp.async.wait_group 1;");
        __syncthreads();
        if (c < 14) ISSUE(c + 2);

        int s = c % 3;
        uint32_t aB = smb + s * STG_BYTES + aL;
        uint32_t bB = smb + s * STG_BYTES + TILE_BYTES + bL;

        unsigned af[2][4];
        ldsm4(af[0], aB);
        ldsm4(af[1], aB + 16 * 48);
#pragma unroll
        for (int p = 0; p < 4; p++) {
            unsigned bf[4];
            ldsm4(bf, bB + p * (16 * 48));
#pragma unroll
            for (int mt = 0; mt < 2; mt++) {
                mma_f16(acc[mt][2 * p],     af[mt], bf[0], bf[2]);
                mma_f16(acc[mt][2 * p + 1], af[mt], bf[1], bf[3]);
            }
        }
    }
#undef ISSUE

    float pc[8][2];
#pragma unroll
    for (int nt = 0; nt < 8; nt++) { pc[nt][0] = 0.f; pc[nt][1] = 0.f; }

#pragma unroll
    for (int mt = 0; mt < 2; mt++) {
#pragma unroll
        for (int rr = 0; rr < 2; rr++) {
            int rIn = wm * 32 + mt * 16 + rr * 8 + (lane >> 2);
            int row = mbase + rIn;
            bool ok = (row < M);
#pragma unroll
            for (int nt = 0; nt < 8; nt++) {
                float v0 = acc[mt][nt][rr * 2], v1 = acc[mt][nt][rr * 2 + 1];
                if (ok) {
                    int col = nbase + wn * 64 + nt * 8 + (lane & 3) * 2;
                    __half2 hv = __floats2half2_rn(v0, v1);
                    *(__half2*)&O[(((size_t)mtile * 16 + (col >> 4)) * 128 + rIn) * 16
                                  + (col & 15)] = hv;
                    pc[nt][0] += fabsf(v0);
                    pc[nt][1] += fabsf(v1);
                }
            }
        }
    }
#pragma unroll
    for (int nt = 0; nt < 8; nt++) {
#pragma unroll
        for (int j = 0; j < 2; j++) {
            float s = pc[nt][j];
            s += __shfl_xor_sync(0xFFFFFFFFu, s, 4);
            s += __shfl_xor_sync(0xFFFFFFFFu, s, 8);
            s += __shfl_xor_sync(0xFFFFFFFFu, s, 16);
            pc[nt][j] = s;
        }
    }
    if (lane < 4) {
#pragma unroll
        for (int nt = 0; nt < 8; nt++)
#pragma unroll
            for (int j = 0; j < 2; j++)
                atomicAdd(&g_rad[par][b * HH + nbase + wn * 64 + nt * 8 + lane * 2 + j],
                          pc[nt][j]);
    }
}

// ---------------------------------------------------------------------------
// prep_final: lam_31/delta_31/headpost_31, zero radout, fill B'o = lam⊙W_o.
// grid (BB, 9). Reads headpre[1], rad[1].
// ---------------------------------------------------------------------------
__global__ void prep_final_kernel(const float* __restrict__ W_o)
{
    int b = blockIdx.x, z = blockIdx.y, tid = threadIdx.x;
    if (z == 8) {
        float lam, mu, de;
        float hp0 = g_headpre[1][b * HH + tid];
        deepz(hp0, g_rad[1][b * HH + tid], lam, mu, de);
        g_headpost[b * HH + tid] = lam * hp0 + mu;
        g_delta[b * HH + tid] = de;
        if (tid < NOUT) g_radout[b * NOUT + tid] = 0.f;
        return;
    }
    __shared__ float s_lam[32];
    if (tid < 32) {
        int k = z * 32 + tid;
        float lam, mu, de;
        deepz(g_headpre[1][b * HH + k], g_rad[1][b * HH + k], lam, mu, de);
        s_lam[tid] = lam;
    }
    __syncthreads();
    int n = tid & 63;
    int kb = tid >> 6;   // 0..3
#pragma unroll
    for (int j = 0; j < 8; j++) {
        int kk = kb + j * 4;           // 0..31
        int k = z * 32 + kk;
        float v = s_lam[kk] * W_o[k * NOUT + n];
        g_Bo[(((size_t)b * 16 + (k >> 4)) * 64 + n) * 24 + (k & 15)]
            = __float2half_rn(v);
    }
}

// ---------------------------------------------------------------------------
// Final projection via fp16 MMA: radout[b,j] += sum_r |row_r @ B'o[:,j]|
// grid (78, BB), 256 threads.
// ---------------------------------------------------------------------------
__global__ void __launch_bounds__(256, 2)
final_mma_kernel()
{
    extern __shared__ char sm[];
    uint32_t smb = smem_u32(sm);
    int b = blockIdx.y;
    int mtile = blockIdx.x;
    const __half* A = g_state[1] + (size_t)b * EMAX * HH;
    const __half* Bo = g_Bo + (size_t)b * 16 * 1536;

    int tid = threadIdx.x;
    int w = tid >> 5, lane = tid & 31;
    int aRow = tid >> 1, aHalf = tid & 1;
    int bRow = tid / 3, bPart = tid - bRow * 3;   // tid<192 valid

#define FISSUE(c) do {                                                         \
    int _s = (c) % 3;                                                          \
    uint32_t _sa = smb + _s * FIN_STG;                                         \
    cpa16(_sa + aRow * 48 + aHalf * 16,                                        \
          A + (((size_t)mtile * 16 + (c)) * 128 + aRow) * 16 + aHalf * 8);     \
    if (tid < 192)                                                             \
        cpa16(_sa + TILE_BYTES + bRow * 48 + bPart * 16,                       \
              Bo + (size_t)(c) * 1536 + bRow * 24 + bPart * 8);                \
    asm volatile("cp.async.commit_group;");                                    \
} while (0)

    float acc[8][4];
#pragma unroll
    for (int nt = 0; nt < 8; nt++)
#pragma unroll
        for (int e = 0; e < 4; e++) acc[nt][e] = 0.f;

    FISSUE(0);
    FISSUE(1);

    uint32_t aL = (uint32_t)((w * 16 + (lane & 15)) * 48 + ((lane >> 4) << 4));
    uint32_t bL = (uint32_t)(((lane & 15)) * 48 + ((lane >> 4) << 4));

    for (int c = 0; c < 16; c++) {
        asm volatile("cp.async.wait_group 1;");
        __syncthreads();
        if (c < 14) FISSUE(c + 2);

        int s = c % 3;
        uint32_t aB = smb + s * FIN_STG + aL;
        uint32_t bB = smb + s * FIN_STG + TILE_BYTES + bL;

        unsigned af[4];
        ldsm4(af, aB);
#pragma unroll
        for (int p = 0; p < 4; p++) {
            unsigned bf[4];
            ldsm4(bf, bB + p * (16 * 48));
            mma_f16(acc[2 * p],     af, bf[0], bf[2]);
            mma_f16(acc[2 * p + 1], af, bf[1], bf[3]);
        }
    }
#undef FISSUE

    float pc[8][2];
#pragma unroll
    for (int nt = 0; nt < 8; nt++) {
        pc[nt][0] = fabsf(acc[nt][0]) + fabsf(acc[nt][2]);
        pc[nt][1] = fabsf(acc[nt][1]) + fabsf(acc[nt][3]);
    }
#pragma unroll
    for (int nt = 0; nt < 8; nt++) {
#pragma unroll
        for (int j = 0; j < 2; j++) {
            float s = pc[nt][j];
            s += __shfl_xor_sync(0xFFFFFFFFu, s, 4);
            s += __shfl_xor_sync(0xFFFFFFFFu, s, 8);
            s += __shfl_xor_sync(0xFFFFFFFFu, s, 16);
            pc[nt][j] = s;
        }
    }
    if (lane < 4) {
#pragma unroll
        for (int nt = 0; nt < 8; nt++)
#pragma unroll
            for (int j = 0; j < 2; j++)
                atomicAdd(&g_radout[b * NOUT + nt * 8 + lane * 2 + j], pc[nt][j]);
    }
}

// ---------------------------------------------------------------------------
// Combine
// ---------------------------------------------------------------------------
__global__ void combine_kernel(const float* __restrict__ W_o,
                               const float* __restrict__ b_o,
                               float* __restrict__ out)
{
    int b = blockIdx.x, j = threadIdx.x;
    float head = b_o[j];
    float radd = 0.f;
#pragma unroll 8
    for (int k = 0; k < HH; k++) {
        float wv = W_o[k * NOUT + j];
        head += g_headpost[b * HH + k] * wv;
        radd += fabsf(g_delta[b * HH + k]) * fabsf(wv);
    }
    float r = g_radout[b * NOUT + j] + radd;
    out[b * NOUT + j]             = head - r;
    out[BB * NOUT + b * NOUT + j] = head + r;
}

// ---------------------------------------------------------------------------
extern "C" void kernel_launch(void* const* d_in, const int* in_sizes, int n_in,
                              void* d_out, int out_size)
{
    const float* X    = (const float*)d_in[0];
    const float* eps  = (const float*)d_in[1];
    const float* W_ih = (const float*)d_in[2];
    const float* W_hh = (const float*)d_in[3];
    const float* b_ih = (const float*)d_in[4];
    const float* b_hh = (const float*)d_in[5];
    const float* W_o  = (const float*)d_in[6];
    const float* b_o  = (const float*)d_in[7];
    float* out = (float*)d_out;

    cudaFuncSetAttribute(step_kernel,
                         cudaFuncAttributeMaxDynamicSharedMemorySize, GT_SMEM);
    cudaFuncSetAttribute(final_mma_kernel,
                         cudaFuncAttributeMaxDynamicSharedMemorySize, FIN_SMEM);

    step0_kernel<<<BB, HH>>>(X, eps, W_ih, b_ih, b_hh);

    int E = NIN;
    for (int t = 1; t < TT; t++) {
        int pp = (t - 1) & 1;
        int mtiles = (E + 127) / 128;
        step_kernel<<<dim3(mtiles + 3, 2, BB), 256, GT_SMEM>>>(
            X, eps, W_ih, W_hh, b_ih, b_hh, t, E, pp);
        E += HH + NIN;
    }

    // E == 9984, state in g_state[1], headpre/rad parity 1
    prep_final_kernel<<<dim3(BB, 9), 256>>>(W_o);
    final_mma_kernel<<<dim3(NTILES, BB), 256, FIN_SMEM>>>();
    combine_kernel<<<BB, NOUT>>>(W_o, b_o, out);
}

// round 14
// speedup vs baseline: 1.2936x; 1.2936x over previous
#include <cuda_runtime.h>
#include <cuda_fp16.h>
#include <math.h>
#include <stdint.h>

// Problem constants
#define TT   32
#define BB   32
#define NIN  64
#define HH   256
#define NOUT 64
#define EMAX 9984          // 78 * 128 exactly
#define NTILES 78
#define CLMIN (-2.0f)
#define CLMAX ( 2.0f)
#define NCTA 296           // 148 SMs x 2 CTAs resident (GB300 has 152 SMs)

// ------- device state (no allocations allowed) -------
__device__ __half g_state[2][(size_t)BB * EMAX * HH];
__device__ __half g_Bp[(size_t)BB * 2 * 16 * 3072];
__device__ __half g_Bo[(size_t)BB * 16 * 64 * 24];
__device__ float g_rad[2][BB * HH];
__device__ float g_headpre[2][BB * HH];
__device__ float g_delta[BB * HH];
__device__ float g_headpost[BB * HH];
__device__ float g_radout[BB * NOUT];
__device__ unsigned g_count;
__device__ unsigned g_sense;

// ------- helpers -------
__device__ __forceinline__ uint32_t smem_u32(const void* p) {
    uint32_t a;
    asm("{ .reg .u64 t; cvta.to.shared.u64 t, %1; cvt.u32.u64 %0, t; }" : "=r"(a) : "l"(p));
    return a;
}
__device__ __forceinline__ void ldsm4(unsigned r[4], uint32_t addr) {
    asm volatile("ldmatrix.sync.aligned.m8n8.x4.shared.b16 {%0,%1,%2,%3}, [%4];"
                 : "=r"(r[0]), "=r"(r[1]), "=r"(r[2]), "=r"(r[3]) : "r"(addr));
}
__device__ __forceinline__ void mma_f16(float* c, const unsigned a[4],
                                        unsigned b0, unsigned b1) {
    asm volatile("mma.sync.aligned.m16n8k16.row.col.f32.f16.f16.f32 "
                 "{%0,%1,%2,%3},{%4,%5,%6,%7},{%8,%9},{%0,%1,%2,%3};"
                 : "+f"(c[0]), "+f"(c[1]), "+f"(c[2]), "+f"(c[3])
                 : "r"(a[0]), "r"(a[1]), "r"(a[2]), "r"(a[3]), "r"(b0), "r"(b1));
}
__device__ __forceinline__ void cpa16(uint32_t dst, const void* src) {
    asm volatile("cp.async.cg.shared.global [%0], [%1], 16;" :: "r"(dst), "l"(src));
}
__device__ __forceinline__ void deepz(float head, float rad,
                                      float& lam, float& mu, float& delta) {
    float l = head - rad, u = head + rad;
    float tl = tanhf(l), tu = tanhf(u);
    lam = fminf(1.f - tl * tl, 1.f - tu * tu);
    mu    = 0.5f * (tu + tl - lam * (u + l));
    delta = 0.5f * (tu - tl - lam * (u - l));
}
// Sense-reversing grid barrier. All NCTA CTAs must call.
__device__ __forceinline__ void gbar(unsigned* lsense) {
    __syncthreads();
    if (threadIdx.x == 0) {
        unsigned s = *lsense ^ 1u;
        *lsense = s;
        __threadfence();
        if (atomicAdd(&g_count, 1u) == NCTA - 1u) {
            g_count = 0u;
            __threadfence();
            atomicExch(&g_sense, s);
        } else {
            unsigned v;
            do {
                asm volatile("ld.acquire.gpu.global.u32 %0, [%1];"
                             : "=r"(v) : "l"(&g_sense) : "memory");
                if (v != s) __nanosleep(64);
            } while (v != s);
        }
    }
    __syncthreads();
}

#define TILE_BYTES 6144      // 128 rows * 48B pitch
#define STG_BYTES  12288
#define GT_SMEM    (3 * STG_BYTES)
#define FIN_STG    9216
#define FIN_SMEM   (3 * FIN_STG)

// ---------------------------------------------------------------------------
// Step 0: initial x-block rows (fp16 tiled), head_pre_0, rad[0], barrier reset
// ---------------------------------------------------------------------------
__global__ void step0_kernel(const float* __restrict__ X,
                             const float* __restrict__ eps,
                             const float* __restrict__ W_ih,
                             const float* __restrict__ b_ih,
                             const float* __restrict__ b_hh)
{
    int b = blockIdx.x;
    int tid = threadIdx.x;
    __shared__ float s_hx[NIN], s_w[NIN];
    if (b == 0 && tid == 0) { g_count = 0u; g_sense = 0u; }
    if (tid < NIN) {
        float x = X[b * NIN + tid];
        float e = eps[b];
        float l = fmaxf(x - e, CLMIN);
        float u = fminf(x + e, CLMAX);
        s_hx[tid] = 0.5f * (l + u);
        s_w[tid]  = 0.5f * (u - l);
    }
    __syncthreads();
    int h = tid;
    float hp = b_ih[h] + b_hh[h];
    float rad = 0.f;
    __half* st = g_state[0] + (size_t)b * EMAX * HH;
    int chunk = h >> 4, kh = h & 15;
#pragma unroll 8
    for (int i = 0; i < NIN; i++) {
        float wv = W_ih[i * HH + h];
        float rowv = s_w[i] * wv;
        hp += s_hx[i] * wv;
        __half hv = __float2half_rn(rowv);
        rad += fabsf(__half2float(hv));
        st[((size_t)chunk * 128 + i) * 16 + kh] = hv;
    }
    g_headpre[0][b * HH + h] = hp;
    g_rad[0][b * HH + h] = rad;
}

// ---------------------------------------------------------------------------
// Persistent step kernel: all 31 recurrence steps in one launch.
// Per step: gbar | phase A: B' prep (256 units) + appends (64 units)
//         | gbar | phase B: head recurrence (64 units) + gemm tiles.
// ---------------------------------------------------------------------------
__global__ void __launch_bounds__(256, 2)
persist_kernel(const float* __restrict__ X,
               const float* __restrict__ eps,
               const float* __restrict__ W_ih,
               const float* __restrict__ W_hh,
               const float* __restrict__ b_ih,
               const float* __restrict__ b_hh)
{
    extern __shared__ char sm[];
    int tid = threadIdx.x;
    int cta = blockIdx.x;
    unsigned lsense = 0;

    for (int t = 1; t < TT; t++) {
        int pp = (t - 1) & 1;
        int par = pp ^ 1;
        int Eprev = NIN + (HH + NIN) * (t - 1);
        int mtiles = (Eprev + 127) >> 7;
        const float* Xt = X + (size_t)t * BB * NIN;
        __half* O = g_state[par] + 0;   // per-unit offset added below

        gbar(&lsense);

        // ================= phase A =================
        for (int u = cta; u < 320; u += NCTA) {
            __syncthreads();
            if (u < 256) {
                // ---- B' prep quarter: g=(b,nhalf), q = chunk quarter ----
                int g = u >> 2, q = u & 3;
                int b = g >> 1, nhalf = g & 1, nbase = nhalf * 128;
                float* s_lam = (float*)sm;   // 64
                if (tid < 64) {
                    float lam, mu, de;
                    int k = q * 64 + tid;
                    deepz(g_headpre[pp][b * HH + k], g_rad[pp][b * HH + k], lam, mu, de);
                    s_lam[tid] = lam;
                }
                if (q == 0 && tid >= 128)
                    g_rad[par][b * HH + nbase + (tid - 128)] = 0.f;
                __syncthreads();
                int row = tid >> 1, part = tid & 1;
                __half* dst = g_Bp + (size_t)(b * 2 + nhalf) * 16 * 3072;
#pragma unroll
                for (int c = q * 4; c < q * 4 + 4; c++) {
                    __half hv[8];
#pragma unroll
                    for (int j = 0; j < 8; j++) {
                        int k = c * 16 + part * 8 + j;
                        hv[j] = __float2half_rn(s_lam[k - q * 64] * W_hh[k * HH + nbase + row]);
                    }
                    *(uint4*)&dst[(size_t)c * 3072 + row * 24 + part * 8] = *(uint4*)hv;
                }
            } else {
                // ---- append fresh diag + x rows for cols [nbase, nbase+128) ----
                int g = u - 256;
                int b = g >> 1, nhalf = g & 1, nbase = nhalf * 128;
                __half* Ob = g_state[par] + (size_t)b * EMAX * HH;
                float* sd = (float*)sm;            // 256 delta
                float* swd = (float*)sm + 256;     // 64 x-widths
                {
                    float lam, mu, de;
                    deepz(g_headpre[pp][b * HH + tid], g_rad[pp][b * HH + tid], lam, mu, de);
                    sd[tid] = de;
                }
                if (tid < NIN) {
                    float x = Xt[b * NIN + tid];
                    float e = eps[b];
                    float l = fmaxf(x - e, CLMIN), uu = fminf(x + e, CLMAX);
                    swd[tid] = 0.5f * (uu - l);
                }
                __syncthreads();
#pragma unroll
                for (int task = tid; task < 2048; task += 256) {
                    int i = task >> 3, gg = task & 7;
                    int R = Eprev + i;
                    float d = sd[i];
                    const float4* wr = (const float4*)&W_hh[i * HH + nbase + gg * 16];
                    __half hv[16];
#pragma unroll
                    for (int qq = 0; qq < 4; qq++) {
                        float4 v = wr[qq];
                        hv[qq * 4 + 0] = __float2half_rn(d * v.x);
                        hv[qq * 4 + 1] = __float2half_rn(d * v.y);
                        hv[qq * 4 + 2] = __float2half_rn(d * v.z);
                        hv[qq * 4 + 3] = __float2half_rn(d * v.w);
                    }
                    int chunk = nhalf * 8 + gg;
                    __half* dp = &Ob[(((size_t)(R >> 7) * 16 + chunk) * 128 + (R & 127)) * 16];
                    *(uint4*)&dp[0] = *(uint4*)&hv[0];
                    *(uint4*)&dp[8] = *(uint4*)&hv[8];
                }
#pragma unroll
                for (int task = tid; task < 512; task += 256) {
                    int i = task >> 3, gg = task & 7;
                    int R = Eprev + 256 + i;
                    float d = swd[i];
                    const float4* wr = (const float4*)&W_ih[i * HH + nbase + gg * 16];
                    __half hv[16];
#pragma unroll
                    for (int qq = 0; qq < 4; qq++) {
                        float4 v = wr[qq];
                        hv[qq * 4 + 0] = __float2half_rn(d * v.x);
                        hv[qq * 4 + 1] = __float2half_rn(d * v.y);
                        hv[qq * 4 + 2] = __float2half_rn(d * v.z);
                        hv[qq * 4 + 3] = __float2half_rn(d * v.w);
                    }
                    int chunk = nhalf * 8 + gg;
                    __half* dp = &Ob[(((size_t)(R >> 7) * 16 + chunk) * 128 + (R & 127)) * 16];
                    *(uint4*)&dp[0] = *(uint4*)&hv[0];
                    *(uint4*)&dp[8] = *(uint4*)&hv[8];
                }
            }
        }

        gbar(&lsense);

        // ================= phase B =================
        int nU = 64 + mtiles * 64;
        for (int u = cta; u < nU; u += NCTA) {
            __syncthreads();
            if (u < 64) {
                // ---- head recurrence + fresh/x rad contributions ----
                int b = u >> 1, nhalf = u & 1, nbase = nhalf * 128;
                float* shp = (float*)sm;
                float* sdd = (float*)sm + 256;
                float* shx = (float*)sm + 512;
                float* swd = (float*)sm + 576;
                float* red = (float*)sm + 640;
                {
                    float lam, mu, de;
                    float hp0 = g_headpre[pp][b * HH + tid];
                    deepz(hp0, g_rad[pp][b * HH + tid], lam, mu, de);
                    shp[tid] = lam * hp0 + mu;
                    sdd[tid] = fabsf(de);
                }
                if (tid < NIN) {
                    float x = Xt[b * NIN + tid];
                    float e = eps[b];
                    float l = fmaxf(x - e, CLMIN), uu = fminf(x + e, CLMAX);
                    shx[tid] = 0.5f * (l + uu);
                    swd[tid] = 0.5f * (uu - l);
                }
                __syncthreads();
                int h = nbase + (tid & 127);
                int seg = tid >> 7;
                float hp = 0.f, radc = 0.f;
                int k0 = seg * 128;
#pragma unroll 8
                for (int k = k0; k < k0 + 128; k++) {
                    float wv = W_hh[k * HH + h];
                    hp   += shp[k] * wv;
                    radc += sdd[k] * fabsf(wv);
                }
                if (seg == 1) {
#pragma unroll 8
                    for (int i = 0; i < NIN; i++) {
                        float wv = W_ih[i * HH + h];
                        hp   += shx[i] * wv;
                        radc += swd[i] * fabsf(wv);
                    }
                } else {
                    hp += b_ih[h] + b_hh[h];
                }
                red[tid] = hp;
                red[tid + 256] = radc;
                __syncthreads();
                if (tid < 128) {
                    float hpt = red[tid] + red[tid + 128];
                    float rct = red[tid + 256] + red[tid + 384];
                    g_headpre[par][b * HH + h] = hpt;
                    atomicAdd(&g_rad[par][b * HH + h], rct);
                }
            } else {
                // ---- gemm tile ----
                int v = u - 64;
                int mtile = v % mtiles;
                int r2 = v / mtiles;
                int nhalf = r2 & 1, b = r2 >> 1;
                int nbase = nhalf * 128;
                int mbase = mtile * 128;
                int M = Eprev;
                uint32_t smb = smem_u32(sm);
                const __half* A = g_state[pp] + (size_t)b * EMAX * HH;
                __half* Ob = g_state[par] + (size_t)b * EMAX * HH;
                const __half* Bp = g_Bp + (size_t)(b * 2 + nhalf) * 16 * 3072;

                int w = tid >> 5, lane = tid & 31;
                int aRow = tid >> 1, aHalf = tid & 1;
                int bRow0 = tid / 3, bPart0 = tid - bRow0 * 3;
                int g1 = 256 + tid;
                int bRow1 = g1 / 3, bPart1 = g1 - bRow1 * 3;

#define ISSUE(c) do {                                                          \
    int _s = (c) % 3;                                                          \
    uint32_t _sa = smb + _s * STG_BYTES;                                       \
    cpa16(_sa + aRow * 48 + aHalf * 16,                                        \
          A + (((size_t)mtile * 16 + (c)) * 128 + aRow) * 16 + aHalf * 8);     \
    uint32_t _sb = _sa + TILE_BYTES;                                           \
    cpa16(_sb + bRow0 * 48 + bPart0 * 16,                                      \
          Bp + (size_t)(c) * 3072 + bRow0 * 24 + bPart0 * 8);                  \
    if (tid < 128)                                                             \
        cpa16(_sb + bRow1 * 48 + bPart1 * 16,                                  \
              Bp + (size_t)(c) * 3072 + bRow1 * 24 + bPart1 * 8);              \
    asm volatile("cp.async.commit_group;");                                    \
} while (0)

                float acc[2][8][4];
#pragma unroll
                for (int mt = 0; mt < 2; mt++)
#pragma unroll
                    for (int nt = 0; nt < 8; nt++)
#pragma unroll
                        for (int e = 0; e < 4; e++) acc[mt][nt][e] = 0.f;

                ISSUE(0);
                ISSUE(1);

                int wm = w >> 1, wn = w & 1;
                uint32_t aL = (uint32_t)((wm * 32 + (lane & 15)) * 48 + ((lane >> 4) << 4));
                uint32_t bL = (uint32_t)((wn * 64 + (lane & 15)) * 48 + ((lane >> 4) << 4));

                for (int c = 0; c < 16; c++) {
                    if (c < 15) asm volatile("cp.async.wait_group 1;");
                    else        asm volatile("cp.async.wait_group 0;");
                    __syncthreads();
                    if (c < 14) ISSUE(c + 2);

                    int s = c % 3;
                    uint32_t aB = smb + s * STG_BYTES + aL;
                    uint32_t bB = smb + s * STG_BYTES + TILE_BYTES + bL;

                    unsigned af[2][4];
                    ldsm4(af[0], aB);
                    ldsm4(af[1], aB + 16 * 48);
#pragma unroll
                    for (int p = 0; p < 4; p++) {
                        unsigned bf[4];
                        ldsm4(bf, bB + p * (16 * 48));
#pragma unroll
                        for (int mt = 0; mt < 2; mt++) {
                            mma_f16(acc[mt][2 * p],     af[mt], bf[0], bf[2]);
                            mma_f16(acc[mt][2 * p + 1], af[mt], bf[1], bf[3]);
                        }
                    }
                }
#undef ISSUE

                float pc[8][2];
#pragma unroll
                for (int nt = 0; nt < 8; nt++) { pc[nt][0] = 0.f; pc[nt][1] = 0.f; }

#pragma unroll
                for (int mt = 0; mt < 2; mt++) {
#pragma unroll
                    for (int rr = 0; rr < 2; rr++) {
                        int rIn = wm * 32 + mt * 16 + rr * 8 + (lane >> 2);
                        int row = mbase + rIn;
                        bool ok = (row < M);
#pragma unroll
                        for (int nt = 0; nt < 8; nt++) {
                            float v0 = acc[mt][nt][rr * 2], v1 = acc[mt][nt][rr * 2 + 1];
                            if (ok) {
                                int col = nbase + wn * 64 + nt * 8 + (lane & 3) * 2;
                                __half2 hv = __floats2half2_rn(v0, v1);
                                *(__half2*)&Ob[(((size_t)mtile * 16 + (col >> 4)) * 128 + rIn) * 16
                                               + (col & 15)] = hv;
                                pc[nt][0] += fabsf(v0);
                                pc[nt][1] += fabsf(v1);
                            }
                        }
                    }
                }
#pragma unroll
                for (int nt = 0; nt < 8; nt++) {
#pragma unroll
                    for (int j = 0; j < 2; j++) {
                        float s = pc[nt][j];
                        s += __shfl_xor_sync(0xFFFFFFFFu, s, 4);
                        s += __shfl_xor_sync(0xFFFFFFFFu, s, 8);
                        s += __shfl_xor_sync(0xFFFFFFFFu, s, 16);
                        pc[nt][j] = s;
                    }
                }
                if (lane < 4) {
#pragma unroll
                    for (int nt = 0; nt < 8; nt++)
#pragma unroll
                        for (int j = 0; j < 2; j++)
                            atomicAdd(&g_rad[par][b * HH + nbase + wn * 64 + nt * 8 + lane * 2 + j],
                                      pc[nt][j]);
                }
            }
        }
        (void)O;
    }
}

// ---------------------------------------------------------------------------
// prep_final: lam_31/delta_31/headpost_31, zero radout, fill B'o = lam⊙W_o.
// ---------------------------------------------------------------------------
__global__ void prep_final_kernel(const float* __restrict__ W_o)
{
    int b = blockIdx.x, z = blockIdx.y, tid = threadIdx.x;
    if (z == 8) {
        float lam, mu, de;
        float hp0 = g_headpre[1][b * HH + tid];
        deepz(hp0, g_rad[1][b * HH + tid], lam, mu, de);
        g_headpost[b * HH + tid] = lam * hp0 + mu;
        g_delta[b * HH + tid] = de;
        if (tid < NOUT) g_radout[b * NOUT + tid] = 0.f;
        return;
    }
    __shared__ float s_lam[32];
    if (tid < 32) {
        int k = z * 32 + tid;
        float lam, mu, de;
        deepz(g_headpre[1][b * HH + k], g_rad[1][b * HH + k], lam, mu, de);
        s_lam[tid] = lam;
    }
    __syncthreads();
    int n = tid & 63;
    int kb = tid >> 6;
#pragma unroll
    for (int j = 0; j < 8; j++) {
        int kk = kb + j * 4;
        int k = z * 32 + kk;
        float v = s_lam[kk] * W_o[k * NOUT + n];
        g_Bo[(((size_t)b * 16 + (k >> 4)) * 64 + n) * 24 + (k & 15)]
            = __float2half_rn(v);
    }
}

// ---------------------------------------------------------------------------
// Final projection via fp16 MMA
// ---------------------------------------------------------------------------
__global__ void __launch_bounds__(256, 2)
final_mma_kernel()
{
    extern __shared__ char sm[];
    uint32_t smb = smem_u32(sm);
    int b = blockIdx.y;
    int mtile = blockIdx.x;
    const __half* A = g_state[1] + (size_t)b * EMAX * HH;
    const __half* Bo = g_Bo + (size_t)b * 16 * 1536;

    int tid = threadIdx.x;
    int w = tid >> 5, lane = tid & 31;
    int aRow = tid >> 1, aHalf = tid & 1;
    int bRow = tid / 3, bPart = tid - bRow * 3;

#define FISSUE(c) do {                                                         \
    int _s = (c) % 3;                                                          \
    uint32_t _sa = smb + _s * FIN_STG;                                         \
    cpa16(_sa + aRow * 48 + aHalf * 16,                                        \
          A + (((size_t)mtile * 16 + (c)) * 128 + aRow) * 16 + aHalf * 8);     \
    if (tid < 192)                                                             \
        cpa16(_sa + TILE_BYTES + bRow * 48 + bPart * 16,                       \
              Bo + (size_t)(c) * 1536 + bRow * 24 + bPart * 8);                \
    asm volatile("cp.async.commit_group;");                                    \
} while (0)

    float acc[8][4];
#pragma unroll
    for (int nt = 0; nt < 8; nt++)
#pragma unroll
        for (int e = 0; e < 4; e++) acc[nt][e] = 0.f;

    FISSUE(0);
    FISSUE(1);

    uint32_t aL = (uint32_t)((w * 16 + (lane & 15)) * 48 + ((lane >> 4) << 4));
    uint32_t bL = (uint32_t)(((lane & 15)) * 48 + ((lane >> 4) << 4));

    for (int c = 0; c < 16; c++) {
        if (c < 15) asm volatile("cp.async.wait_group 1;");
        else        asm volatile("cp.async.wait_group 0;");
        __syncthreads();
        if (c < 14) FISSUE(c + 2);

        int s = c % 3;
        uint32_t aB = smb + s * FIN_STG + aL;
        uint32_t bB = smb + s * FIN_STG + TILE_BYTES + bL;

        unsigned af[4];
        ldsm4(af, aB);
#pragma unroll
        for (int p = 0; p < 4; p++) {
            unsigned bf[4];
            ldsm4(bf, bB + p * (16 * 48));
            mma_f16(acc[2 * p],     af, bf[0], bf[2]);
            mma_f16(acc[2 * p + 1], af, bf[1], bf[3]);
        }
    }
#undef FISSUE

    float pc[8][2];
#pragma unroll
    for (int nt = 0; nt < 8; nt++) {
        pc[nt][0] = fabsf(acc[nt][0]) + fabsf(acc[nt][2]);
        pc[nt][1] = fabsf(acc[nt][1]) + fabsf(acc[nt][3]);
    }
#pragma unroll
    for (int nt = 0; nt < 8; nt++) {
#pragma unroll
        for (int j = 0; j < 2; j++) {
            float s = pc[nt][j];
            s += __shfl_xor_sync(0xFFFFFFFFu, s, 4);
            s += __shfl_xor_sync(0xFFFFFFFFu, s, 8);
            s += __shfl_xor_sync(0xFFFFFFFFu, s, 16);
            pc[nt][j] = s;
        }
    }
    if (lane < 4) {
#pragma unroll
        for (int nt = 0; nt < 8; nt++)
#pragma unroll
            for (int j = 0; j < 2; j++)
                atomicAdd(&g_radout[b * NOUT + nt * 8 + lane * 2 + j], pc[nt][j]);
    }
}

// ---------------------------------------------------------------------------
// Combine
// ---------------------------------------------------------------------------
__global__ void combine_kernel(const float* __restrict__ W_o,
                               const float* __restrict__ b_o,
                               float* __restrict__ out)
{
    int b = blockIdx.x, j = threadIdx.x;
    float head = b_o[j];
    float radd = 0.f;
#pragma unroll 8
    for (int k = 0; k < HH; k++) {
        float wv = W_o[k * NOUT + j];
        head += g_headpost[b * HH + k] * wv;
        radd += fabsf(g_delta[b * HH + k]) * fabsf(wv);
    }
    float r = g_radout[b * NOUT + j] + radd;
    out[b * NOUT + j]             = head - r;
    out[BB * NOUT + b * NOUT + j] = head + r;
}

// ---------------------------------------------------------------------------
extern "C" void kernel_launch(void* const* d_in, const int* in_sizes, int n_in,
                              void* d_out, int out_size)
{
    const float* X    = (const float*)d_in[0];
    const float* eps  = (const float*)d_in[1];
    const float* W_ih = (const float*)d_in[2];
    const float* W_hh = (const float*)d_in[3];
    const float* b_ih = (const float*)d_in[4];
    const float* b_hh = (const float*)d_in[5];
    const float* W_o  = (const float*)d_in[6];
    const float* b_o  = (const float*)d_in[7];
    float* out = (float*)d_out;

    cudaFuncSetAttribute(persist_kernel,
                         cudaFuncAttributeMaxDynamicSharedMemorySize, GT_SMEM);
    cudaFuncSetAttribute(final_mma_kernel,
                         cudaFuncAttributeMaxDynamicSharedMemorySize, FIN_SMEM);

    step0_kernel<<<BB, HH>>>(X, eps, W_ih, b_ih, b_hh);
    persist_kernel<<<NCTA, 256, GT_SMEM>>>(X, eps, W_ih, W_hh, b_ih, b_hh);
    prep_final_kernel<<<dim3(BB, 9), 256>>>(W_o);
    final_mma_kernel<<<dim3(NTILES, BB), 256, FIN_SMEM>>>();
    combine_kernel<<<BB, NOUT>>>(W_o, b_o, out);
}

// round 15
// speedup vs baseline: 1.3678x; 1.0574x over previous
#include <cuda_runtime.h>
#include <cuda_fp16.h>
#include <math.h>
#include <stdint.h>

// Problem constants
#define TT   32
#define BB   32
#define NIN  64
#define HH   256
#define NOUT 64
#define EMAX 9984          // 78 * 128 exactly
#define NTILES 78
#define CLMIN (-2.0f)
#define CLMAX ( 2.0f)

// ------- device state (no allocations allowed) -------
// Error-row state, fp16, tiled: idx = ((tile*16 + chunk)*128 + row)*16 + h
__device__ __half g_state[2][(size_t)BB * EMAX * HH];
// Fixed B image: fp16(W_hh^T), [nhalf][chunk16][row128][pitch24]
__device__ __half g_Bfix[2 * 16 * 3072];
// B'o = fp16(lam_31 ⊙ W_o), [b][chunk16][row64][pitch24]
__device__ __half g_Bo[(size_t)BB * 16 * 64 * 24];
__device__ float g_rad[3][BB * HH];       // 3-way rotation
__device__ float g_headpre[2][BB * HH];   // parity ping-pong
__device__ float g_delta[BB * HH];
__device__ float g_headpost[BB * HH];
__device__ float g_radout[BB * NOUT];

// ------- helpers -------
__device__ __forceinline__ uint32_t smem_u32(const void* p) {
    uint32_t a;
    asm("{ .reg .u64 t; cvta.to.shared.u64 t, %1; cvt.u32.u64 %0, t; }" : "=r"(a) : "l"(p));
    return a;
}
__device__ __forceinline__ void ldsm4(unsigned r[4], uint32_t addr) {
    asm volatile("ldmatrix.sync.aligned.m8n8.x4.shared.b16 {%0,%1,%2,%3}, [%4];"
                 : "=r"(r[0]), "=r"(r[1]), "=r"(r[2]), "=r"(r[3]) : "r"(addr));
}
__device__ __forceinline__ void mma_f16(float* c, const unsigned a[4],
                                        unsigned b0, unsigned b1) {
    asm volatile("mma.sync.aligned.m16n8k16.row.col.f32.f16.f16.f32 "
                 "{%0,%1,%2,%3},{%4,%5,%6,%7},{%8,%9},{%0,%1,%2,%3};"
                 : "+f"(c[0]), "+f"(c[1]), "+f"(c[2]), "+f"(c[3])
                 : "r"(a[0]), "r"(a[1]), "r"(a[2]), "r"(a[3]), "r"(b0), "r"(b1));
}
__device__ __forceinline__ void cpa16(uint32_t dst, const void* src) {
    asm volatile("cp.async.cg.shared.global [%0], [%1], 16;" :: "r"(dst), "l"(src));
}
__device__ __forceinline__ void deepz(float head, float rad,
                                      float& lam, float& mu, float& delta) {
    float l = head - rad, u = head + rad;
    float tl = tanhf(l), tu = tanhf(u);
    lam = fminf(1.f - tl * tl, 1.f - tu * tu);
    mu    = 0.5f * (tu + tl - lam * (u + l));
    delta = 0.5f * (tu - tl - lam * (u - l));
}

// SMEM layout (step gemm): A bufs 2*6144 @0, B bufs 3*6144 @12288, lamh @30720
#define SM_BOFF   12288
#define SM_LAMH   30720
#define GT_SMEM   31232
#define TILE_BYTES 6144
#define FIN_STG   9216
#define FIN_SMEM  (3 * FIN_STG)

// ---------------------------------------------------------------------------
// prepB: fixed fp16 W_hh^T image (runs once per replay).
// grid (2,2): x=nhalf, y=chunk-half. 256 threads.
// ---------------------------------------------------------------------------
__global__ void prepB_kernel(const float* __restrict__ W_hh)
{
    int nhalf = blockIdx.x, cpart = blockIdx.y, tid = threadIdx.x;
    int nbase = nhalf * 128;
    int row = tid >> 1, part = tid & 1;
#pragma unroll
    for (int c = cpart * 8; c < cpart * 8 + 8; c++) {
        __half hv[8];
#pragma unroll
        for (int j = 0; j < 8; j++) {
            int k = c * 16 + part * 8 + j;
            hv[j] = __float2half_rn(W_hh[k * HH + nbase + row]);
        }
        *(uint4*)&g_Bfix[((size_t)nhalf * 16 + c) * 3072 + row * 24 + part * 8] = *(uint4*)hv;
    }
}

// ---------------------------------------------------------------------------
// Step 0: initial x-block rows (fp16 tiled), head_pre_0, rad[0]; zero rad[1]
// ---------------------------------------------------------------------------
__global__ void step0_kernel(const float* __restrict__ X,
                             const float* __restrict__ eps,
                             const float* __restrict__ W_ih,
                             const float* __restrict__ b_ih,
                             const float* __restrict__ b_hh)
{
    int b = blockIdx.x;
    int tid = threadIdx.x;
    __shared__ float s_hx[NIN], s_w[NIN];
    if (tid < NIN) {
        float x = X[b * NIN + tid];
        float e = eps[b];
        float l = fmaxf(x - e, CLMIN);
        float u = fminf(x + e, CLMAX);
        s_hx[tid] = 0.5f * (l + u);
        s_w[tid]  = 0.5f * (u - l);
    }
    __syncthreads();
    int h = tid;
    float hp = b_ih[h] + b_hh[h];
    float rad = 0.f;
    __half* st = g_state[0] + (size_t)b * EMAX * HH;
    int chunk = h >> 4, kh = h & 15;
#pragma unroll 8
    for (int i = 0; i < NIN; i++) {
        float wv = W_ih[i * HH + h];
        float rowv = s_w[i] * wv;
        hp += s_hx[i] * wv;
        __half hv = __float2half_rn(rowv);
        rad += fabsf(__half2float(hv));
        st[((size_t)chunk * 128 + i) * 16 + kh] = hv;
    }
    g_headpre[0][b * HH + h] = hp;
    g_rad[0][b * HH + h] = rad;
    g_rad[1][b * HH + h] = 0.f;      // step 1 writes rad[1]
}

// ---------------------------------------------------------------------------
// Step kernel: gemm tiles (lam folded into A at stage time) + append + head.
// grid (mtiles + 2, 2, BB), 256 threads.
//   bx in [0,mtiles)  : gemm tile
//   bx == mtiles      : fresh diag + x rows append
//   bx == mtiles+1    : head recurrence + fresh/x rad parts + zero rad[rz]
// rad indices: rr=(t-1)%3 (read), rw=t%3 (write), rz=(t+1)%3 (zero).
// ---------------------------------------------------------------------------
__global__ void __launch_bounds__(256, 2)
step_kernel(const float* __restrict__ X,
            const float* __restrict__ eps,
            const float* __restrict__ W_ih,
            const float* __restrict__ W_hh,
            const float* __restrict__ b_ih,
            const float* __restrict__ b_hh,
            int t, int Eprev, int pp, int rr, int rw, int rz)
{
    extern __shared__ char sm[];
    int b = blockIdx.z;
    int nhalf = blockIdx.y;
    int nbase = nhalf * 128;
    int tid = threadIdx.x;
    int mtiles = gridDim.x - 2;
    int bx = blockIdx.x;
    int par = pp ^ 1;
    const float* Xt = X + (size_t)t * BB * NIN;
    __half* O = g_state[par] + (size_t)b * EMAX * HH;

    if (bx == mtiles) {
        // ---- fresh diag rows + x rows for cols [nbase, nbase+128) ----
        float* sd = (float*)sm;            // 256 delta
        float* sw = (float*)sm + 256;      // 64 x-widths
        {
            float lam, mu, de;
            deepz(g_headpre[pp][b * HH + tid], g_rad[rr][b * HH + tid], lam, mu, de);
            sd[tid] = de;
        }
        if (tid < NIN) {
            float x = Xt[b * NIN + tid];
            float e = eps[b];
            float l = fmaxf(x - e, CLMIN), u = fminf(x + e, CLMAX);
            sw[tid] = 0.5f * (u - l);
        }
        __syncthreads();
#pragma unroll
        for (int task = tid; task < 2048; task += 256) {
            int i = task >> 3, g = task & 7;
            int R = Eprev + i;
            float d = sd[i];
            const float4* wr = (const float4*)&W_hh[i * HH + nbase + g * 16];
            __half hv[16];
#pragma unroll
            for (int q = 0; q < 4; q++) {
                float4 v = wr[q];
                hv[q * 4 + 0] = __float2half_rn(d * v.x);
                hv[q * 4 + 1] = __float2half_rn(d * v.y);
                hv[q * 4 + 2] = __float2half_rn(d * v.z);
                hv[q * 4 + 3] = __float2half_rn(d * v.w);
            }
            int chunk = nhalf * 8 + g;
            __half* dp = &O[(((size_t)(R >> 7) * 16 + chunk) * 128 + (R & 127)) * 16];
            *(uint4*)&dp[0] = *(uint4*)&hv[0];
            *(uint4*)&dp[8] = *(uint4*)&hv[8];
        }
#pragma unroll
        for (int task = tid; task < 512; task += 256) {
            int i = task >> 3, g = task & 7;
            int R = Eprev + 256 + i;
            float d = sw[i];
            const float4* wr = (const float4*)&W_ih[i * HH + nbase + g * 16];
            __half hv[16];
#pragma unroll
            for (int q = 0; q < 4; q++) {
                float4 v = wr[q];
                hv[q * 4 + 0] = __float2half_rn(d * v.x);
                hv[q * 4 + 1] = __float2half_rn(d * v.y);
                hv[q * 4 + 2] = __float2half_rn(d * v.z);
                hv[q * 4 + 3] = __float2half_rn(d * v.w);
            }
            int chunk = nhalf * 8 + g;
            __half* dp = &O[(((size_t)(R >> 7) * 16 + chunk) * 128 + (R & 127)) * 16];
            *(uint4*)&dp[0] = *(uint4*)&hv[0];
            *(uint4*)&dp[8] = *(uint4*)&hv[8];
        }
        return;
    }
    if (bx == mtiles + 1) {
        // ---- head recurrence + fresh/x rad parts; zero rad[rz] ----
        if (tid < 128) g_rad[rz][b * HH + nbase + tid] = 0.f;
        float* shp = (float*)sm;
        float* sdd = (float*)sm + 256;
        float* shx = (float*)sm + 512;
        float* sw  = (float*)sm + 576;
        float* red = (float*)sm + 640;
        {
            float lam, mu, de;
            float hp0 = g_headpre[pp][b * HH + tid];
            deepz(hp0, g_rad[rr][b * HH + tid], lam, mu, de);
            shp[tid] = lam * hp0 + mu;
            sdd[tid] = fabsf(de);
        }
        if (tid < NIN) {
            float x = Xt[b * NIN + tid];
            float e = eps[b];
            float l = fmaxf(x - e, CLMIN), u = fminf(x + e, CLMAX);
            shx[tid] = 0.5f * (l + u);
            sw[tid]  = 0.5f * (u - l);
        }
        __syncthreads();
        int h = nbase + (tid & 127);
        int seg = tid >> 7;
        float hp = 0.f, radc = 0.f;
        int k0 = seg * 128;
#pragma unroll 8
        for (int k = k0; k < k0 + 128; k++) {
            float wv = W_hh[k * HH + h];
            hp   += shp[k] * wv;
            radc += sdd[k] * fabsf(wv);
        }
        if (seg == 1) {
#pragma unroll 8
            for (int i = 0; i < NIN; i++) {
                float wv = W_ih[i * HH + h];
                hp   += shx[i] * wv;
                radc += sw[i] * fabsf(wv);
            }
        } else {
            hp += b_ih[h] + b_hh[h];
        }
        red[tid] = hp;
        red[tid + 256] = radc;
        __syncthreads();
        if (tid < 128) {
            float hpt = red[tid] + red[tid + 128];
            float rct = red[tid + 256] + red[tid + 384];
            g_headpre[par][b * HH + h] = hpt;
            atomicAdd(&g_rad[rw][b * HH + h], rct);
        }
        return;
    }

    // ---- gemm tile path: out = (A ⊙ lam) @ W_hh^T ----
    uint32_t smb = smem_u32(sm);
    int mtile = bx;
    int mbase = mtile * 128;
    int M = Eprev;
    const __half* A = g_state[pp] + (size_t)b * EMAX * HH;
    const __half* Bf = g_Bfix + (size_t)nhalf * 16 * 3072;
    __half* s_lamh = (__half*)(sm + SM_LAMH);

    // lam for all 256 k, as fp16
    {
        float lam, mu, de;
        deepz(g_headpre[pp][b * HH + tid], g_rad[rr][b * HH + tid], lam, mu, de);
        s_lamh[tid] = __float2half_rn(lam);
    }

    int w = tid >> 5, lane = tid & 31;
    int aRow = tid >> 1, aPart = tid & 1;
    int bRow0 = tid / 3, bPart0 = tid - bRow0 * 3;
    int g1 = 256 + tid;
    int bRow1 = g1 / 3, bPart1 = g1 - bRow1 * 3;

#define BISSUE(c) do {                                                         \
    int _s = (c) % 3;                                                          \
    uint32_t _sb = smb + SM_BOFF + _s * TILE_BYTES;                            \
    cpa16(_sb + bRow0 * 48 + bPart0 * 16,                                      \
          Bf + (size_t)(c) * 3072 + bRow0 * 24 + bPart0 * 8);                  \
    if (tid < 128)                                                             \
        cpa16(_sb + bRow1 * 48 + bPart1 * 16,                                  \
              Bf + (size_t)(c) * 3072 + bRow1 * 24 + bPart1 * 8);              \
    asm volatile("cp.async.commit_group;");                                    \
} while (0)

    uint4 areg;
#define ALOAD(c) do {                                                          \
    areg = *(const uint4*)(A + (((size_t)mtile * 16 + (c)) * 128 + aRow) * 16  \
                           + aPart * 8);                                       \
} while (0)
#define ASTORE(c, buf) do {                                                    \
    uint4 lv = *(uint4*)(s_lamh + (c) * 16 + aPart * 8);                       \
    uint4 rres;                                                                \
    __half2* ah = (__half2*)&areg;                                             \
    __half2* lh = (__half2*)&lv;                                               \
    __half2* rh = (__half2*)&rres;                                             \
    rh[0] = __hmul2(ah[0], lh[0]);                                             \
    rh[1] = __hmul2(ah[1], lh[1]);                                             \
    rh[2] = __hmul2(ah[2], lh[2]);                                             \
    rh[3] = __hmul2(ah[3], lh[3]);                                             \
    *(uint4*)(sm + (buf) * TILE_BYTES + aRow * 48 + aPart * 16) = rres;        \
} while (0)

    float acc[2][8][4];
#pragma unroll
    for (int mt = 0; mt < 2; mt++)
#pragma unroll
        for (int nt = 0; nt < 8; nt++)
#pragma unroll
            for (int e = 0; e < 4; e++) acc[mt][nt][e] = 0.f;

    BISSUE(0);
    BISSUE(1);
    ALOAD(0);
    __syncthreads();          // s_lamh visible
    ASTORE(0, 0);

    int wm = w >> 1, wn = w & 1;
    uint32_t aL = (uint32_t)((wm * 32 + (lane & 15)) * 48 + ((lane >> 4) << 4));
    uint32_t bL = (uint32_t)((wn * 64 + (lane & 15)) * 48 + ((lane >> 4) << 4));

    for (int c = 0; c < 16; c++) {
        if (c < 15) ALOAD(c + 1);
        if (c < 15) asm volatile("cp.async.wait_group 1;");
        else        asm volatile("cp.async.wait_group 0;");
        __syncthreads();
        if (c < 14) BISSUE(c + 2);

        uint32_t aB = smb + (c & 1) * TILE_BYTES + aL;
        uint32_t bB = smb + SM_BOFF + (c % 3) * TILE_BYTES + bL;

        unsigned af[2][4];
        ldsm4(af[0], aB);
        ldsm4(af[1], aB + 16 * 48);
#pragma unroll
        for (int p = 0; p < 4; p++) {
            unsigned bf[4];
            ldsm4(bf, bB + p * (16 * 48));
#pragma unroll
            for (int mt = 0; mt < 2; mt++) {
                mma_f16(acc[mt][2 * p],     af[mt], bf[0], bf[2]);
                mma_f16(acc[mt][2 * p + 1], af[mt], bf[1], bf[3]);
            }
        }
        if (c < 15) ASTORE(c + 1, (c + 1) & 1);
    }
#undef BISSUE
#undef ALOAD
#undef ASTORE

    float pc[8][2];
#pragma unroll
    for (int nt = 0; nt < 8; nt++) { pc[nt][0] = 0.f; pc[nt][1] = 0.f; }

#pragma unroll
    for (int mt = 0; mt < 2; mt++) {
#pragma unroll
        for (int rq = 0; rq < 2; rq++) {
            int rIn = wm * 32 + mt * 16 + rq * 8 + (lane >> 2);
            int row = mbase + rIn;
            bool ok = (row < M);
#pragma unroll
            for (int nt = 0; nt < 8; nt++) {
                float v0 = acc[mt][nt][rq * 2], v1 = acc[mt][nt][rq * 2 + 1];
                if (ok) {
                    int col = nbase + wn * 64 + nt * 8 + (lane & 3) * 2;
                    __half2 hv = __floats2half2_rn(v0, v1);
                    *(__half2*)&O[(((size_t)mtile * 16 + (col >> 4)) * 128 + rIn) * 16
                                  + (col & 15)] = hv;
                    pc[nt][0] += fabsf(v0);
                    pc[nt][1] += fabsf(v1);
                }
            }
        }
    }
#pragma unroll
    for (int nt = 0; nt < 8; nt++) {
#pragma unroll
        for (int j = 0; j < 2; j++) {
            float s = pc[nt][j];
            s += __shfl_xor_sync(0xFFFFFFFFu, s, 4);
            s += __shfl_xor_sync(0xFFFFFFFFu, s, 8);
            s += __shfl_xor_sync(0xFFFFFFFFu, s, 16);
            pc[nt][j] = s;
        }
    }
    if (lane < 4) {
#pragma unroll
        for (int nt = 0; nt < 8; nt++)
#pragma unroll
            for (int j = 0; j < 2; j++)
                atomicAdd(&g_rad[rw][b * HH + nbase + wn * 64 + nt * 8 + lane * 2 + j],
                          pc[nt][j]);
    }
}

// ---------------------------------------------------------------------------
// prep_final: lam_31/delta_31/headpost_31, zero radout, fill B'o = lam⊙W_o.
// Reads headpre[1], rad[1] (= rad[31%3]).
// ---------------------------------------------------------------------------
__global__ void prep_final_kernel(const float* __restrict__ W_o)
{
    int b = blockIdx.x, z = blockIdx.y, tid = threadIdx.x;
    if (z == 8) {
        float lam, mu, de;
        float hp0 = g_headpre[1][b * HH + tid];
        deepz(hp0, g_rad[1][b * HH + tid], lam, mu, de);
        g_headpost[b * HH + tid] = lam * hp0 + mu;
        g_delta[b * HH + tid] = de;
        if (tid < NOUT) g_radout[b * NOUT + tid] = 0.f;
        return;
    }
    __shared__ float s_lam[32];
    if (tid < 32) {
        int k = z * 32 + tid;
        float lam, mu, de;
        deepz(g_headpre[1][b * HH + k], g_rad[1][b * HH + k], lam, mu, de);
        s_lam[tid] = lam;
    }
    __syncthreads();
    int n = tid & 63;
    int kb = tid >> 6;
#pragma unroll
    for (int j = 0; j < 8; j++) {
        int kk = kb + j * 4;
        int k = z * 32 + kk;
        float v = s_lam[kk] * W_o[k * NOUT + n];
        g_Bo[(((size_t)b * 16 + (k >> 4)) * 64 + n) * 24 + (k & 15)]
            = __float2half_rn(v);
    }
}

// ---------------------------------------------------------------------------
// Final projection via fp16 MMA
// ---------------------------------------------------------------------------
__global__ void __launch_bounds__(256, 2)
final_mma_kernel()
{
    extern __shared__ char sm[];
    uint32_t smb = smem_u32(sm);
    int b = blockIdx.y;
    int mtile = blockIdx.x;
    const __half* A = g_state[1] + (size_t)b * EMAX * HH;
    const __half* Bo = g_Bo + (size_t)b * 16 * 1536;

    int tid = threadIdx.x;
    int w = tid >> 5, lane = tid & 31;
    int aRow = tid >> 1, aHalf = tid & 1;
    int bRow = tid / 3, bPart = tid - bRow * 3;

#define FISSUE(c) do {                                                         \
    int _s = (c) % 3;                                                          \
    uint32_t _sa = smb + _s * FIN_STG;                                         \
    cpa16(_sa + aRow * 48 + aHalf * 16,                                        \
          A + (((size_t)mtile * 16 + (c)) * 128 + aRow) * 16 + aHalf * 8);     \
    if (tid < 192)                                                             \
        cpa16(_sa + TILE_BYTES + bRow * 48 + bPart * 16,                       \
              Bo + (size_t)(c) * 1536 + bRow * 24 + bPart * 8);                \
    asm volatile("cp.async.commit_group;");                                    \
} while (0)

    float acc[8][4];
#pragma unroll
    for (int nt = 0; nt < 8; nt++)
#pragma unroll
        for (int e = 0; e < 4; e++) acc[nt][e] = 0.f;

    FISSUE(0);
    FISSUE(1);

    uint32_t aL = (uint32_t)((w * 16 + (lane & 15)) * 48 + ((lane >> 4) << 4));
    uint32_t bL = (uint32_t)(((lane & 15)) * 48 + ((lane >> 4) << 4));

    for (int c = 0; c < 16; c++) {
        if (c < 15) asm volatile("cp.async.wait_group 1;");
        else        asm volatile("cp.async.wait_group 0;");
        __syncthreads();
        if (c < 14) FISSUE(c + 2);

        int s = c % 3;
        uint32_t aB = smb + s * FIN_STG + aL;
        uint32_t bB = smb + s * FIN_STG + TILE_BYTES + bL;

        unsigned af[4];
        ldsm4(af, aB);
#pragma unroll
        for (int p = 0; p < 4; p++) {
            unsigned bf[4];
            ldsm4(bf, bB + p * (16 * 48));
            mma_f16(acc[2 * p],     af, bf[0], bf[2]);
            mma_f16(acc[2 * p + 1], af, bf[1], bf[3]);
        }
    }
#undef FISSUE

    float pc[8][2];
#pragma unroll
    for (int nt = 0; nt < 8; nt++) {
        pc[nt][0] = fabsf(acc[nt][0]) + fabsf(acc[nt][2]);
        pc[nt][1] = fabsf(acc[nt][1]) + fabsf(acc[nt][3]);
    }
#pragma unroll
    for (int nt = 0; nt < 8; nt++) {
#pragma unroll
        for (int j = 0; j < 2; j++) {
            float s = pc[nt][j];
            s += __shfl_xor_sync(0xFFFFFFFFu, s, 4);
            s += __shfl_xor_sync(0xFFFFFFFFu, s, 8);
            s += __shfl_xor_sync(0xFFFFFFFFu, s, 16);
            pc[nt][j] = s;
        }
    }
    if (lane < 4) {
#pragma unroll
        for (int nt = 0; nt < 8; nt++)
#pragma unroll
            for (int j = 0; j < 2; j++)
                atomicAdd(&g_radout[b * NOUT + nt * 8 + lane * 2 + j], pc[nt][j]);
    }
}

// ---------------------------------------------------------------------------
// Combine
// ---------------------------------------------------------------------------
__global__ void combine_kernel(const float* __restrict__ W_o,
                               const float* __restrict__ b_o,
                               float* __restrict__ out)
{
    int b = blockIdx.x, j = threadIdx.x;
    float head = b_o[j];
    float radd = 0.f;
#pragma unroll 8
    for (int k = 0; k < HH; k++) {
        float wv = W_o[k * NOUT + j];
        head += g_headpost[b * HH + k] * wv;
        radd += fabsf(g_delta[b * HH + k]) * fabsf(wv);
    }
    float r = g_radout[b * NOUT + j] + radd;
    out[b * NOUT + j]             = head - r;
    out[BB * NOUT + b * NOUT + j] = head + r;
}

// ---------------------------------------------------------------------------
extern "C" void kernel_launch(void* const* d_in, const int* in_sizes, int n_in,
                              void* d_out, int out_size)
{
    const float* X    = (const float*)d_in[0];
    const float* eps  = (const float*)d_in[1];
    const float* W_ih = (const float*)d_in[2];
    const float* W_hh = (const float*)d_in[3];
    const float* b_ih = (const float*)d_in[4];
    const float* b_hh = (const float*)d_in[5];
    const float* W_o  = (const float*)d_in[6];
    const float* b_o  = (const float*)d_in[7];
    float* out = (float*)d_out;

    cudaFuncSetAttribute(step_kernel,
                         cudaFuncAttributeMaxDynamicSharedMemorySize, GT_SMEM);
    cudaFuncSetAttribute(final_mma_kernel,
                         cudaFuncAttributeMaxDynamicSharedMemorySize, FIN_SMEM);

    prepB_kernel<<<dim3(2, 2), 256>>>(W_hh);
    step0_kernel<<<BB, HH>>>(X, eps, W_ih, b_ih, b_hh);

    int E = NIN;
    for (int t = 1; t < TT; t++) {
        int pp = (t - 1) & 1;
        int rr = (t - 1) % 3, rw = t % 3, rz = (t + 1) % 3;
        int mtiles = (E + 127) / 128;
        step_kernel<<<dim3(mtiles + 2, 2, BB), 256, GT_SMEM>>>(
            X, eps, W_ih, W_hh, b_ih, b_hh, t, E, pp, rr, rw, rz);
        E += HH + NIN;
    }

    // E == 9984, state in g_state[1]; rad[31%3]=rad[1], headpre[1]
    prep_final_kernel<<<dim3(BB, 9), 256>>>(W_o);
    final_mma_kernel<<<dim3(NTILES, BB), 256, FIN_SMEM>>>();
    combine_kernel<<<BB, NOUT>>>(W_o, b_o, out);
}